// round 11
// baseline (speedup 1.0000x reference)
#include <cuda_runtime.h>
#include <cuda_fp16.h>
#include <cstdint>

#define B 32
#define N 1024
#define M 1024
#define TOL 0.001f
#define MAX_ITER 50
#define BPB 8                  // blocks per batch
#define GRID (B * BPB)         // 256
#define TPB 256                // 8 warps
#define RPB 128                // rows per block
#define WROWS 16               // rows per warp
#define EM105 2.7536449349747158e-5f   // exp(-10.5): scaled-u init (log_u0 = 0)

// ---------------------------------------------------------------------------
__device__ __half   g_K16[(size_t)B * N * M];     // 64 MB, L2-resident
__device__ float    g_partial[2][GRID * M];       // [parity][(b*BPB+sl)*M + c]
__device__ float    g_vbuf[2][B * M];
__device__ int      g_chgBatch[MAX_ITER * B];
__device__ int      g_change[MAX_ITER];
__device__ int      g_chgCount[MAX_ITER];
__device__ unsigned g_batCount[B * 32];           // one cache line per batch
__device__ unsigned g_batGen[B * 32];

__global__ void initKernel() {
    int t = threadIdx.x;
    for (int i = t; i < MAX_ITER * B; i += 256) g_chgBatch[i] = 0;
    for (int i = t; i < MAX_ITER; i += 256) { g_change[i] = 0; g_chgCount[i] = 0; }
    for (int i = t; i < B * 32; i += 256) { g_batCount[i] = 0u; g_batGen[i] = 0u; }
}

// exp(10.5 - 20c), c in [0,1): 2^ri * deg-5 poly(f*ln2). FMA-only.
// trunc err 2.4e-6 << fp16 ulp (4.9e-4).
__device__ __forceinline__ float kexp10(float c) {
    float y  = fmaf(c, -28.853900817779268f, 15.148297929334116f);
    int   ri = __float2int_rn(y);
    float x  = (y - (float)ri) * 0.69314718055994531f;   // |x| <= 0.347
    float p  = 8.3333333333e-3f;                         // 1/120
    p = fmaf(p, x, 4.1666666667e-2f);                    // 1/24
    p = fmaf(p, x, 1.6666666667e-1f);                    // 1/6
    p = fmaf(p, x, 0.5f);
    p = fmaf(p, x, 1.0f);
    p = fmaf(p, x, 1.0f);
    return p * __int_as_float((ri + 127) << 23);
}

// Per-batch sense-reversing barrier (BPB arrivals on a private line).
__device__ __forceinline__ void batchBarrier(int b, unsigned gen) {
    __syncthreads();
    if (threadIdx.x == 0) {
        __threadfence();
        if (atomicAdd(&g_batCount[b * 32], 1u) == BPB - 1) {
            atomicExch(&g_batCount[b * 32], 0u);
            __threadfence();
            atomicExch(&g_batGen[b * 32], gen + 1u);
        } else {
            while (atomicAdd(&g_batGen[b * 32], 0u) < gen + 1u) __nanosleep(32);
        }
        __threadfence();
    }
    __syncthreads();
}

// ---------------------------------------------------------------------------
// Persistent fused Sinkhorn, single-touch sweeps.
//  it=0: convert cost->K16 fused with row sums (v0=1) AND col acc (u1).
//  it>0: per row: load K16 once, row dot -> u_new in-register, col acc.
//  Zero __syncthreads inside a sweep; cross-warp column reduce via smem stage.
// ---------------------------------------------------------------------------
__global__ void __launch_bounds__(TPB, 2) sinkhornKernel(
    const float* __restrict__ cost, const float* __restrict__ src,
    const float* __restrict__ tgt, float* __restrict__ out) {

    __shared__ float sv[M];          // v for this batch
    __shared__ float sacc[8][M];     // per-warp column partial staging (32 KB)
    __shared__ float suAll[RPB];     // final u' for epilogue
    __shared__ float schg[8];
    __shared__ int   sbrk;

    const int t    = threadIdx.x;
    const int w    = t >> 5;
    const int lane = t & 31;
    const int blk  = blockIdx.x;
    const int b    = blk >> 3;
    const int sl   = blk & 7;
    const int rowBase = (b << 10) + (sl << 7);
    const size_t elemBase = (size_t)rowBase << 10;
    const int r0   = w << 4;                       // warp's first block-local row

    const float4* sv4 = (const float4*)sv;
    const __half* Kbase = g_K16 + elemBase;

    // persistent per-lane state: lane j (<16) owns row r0+j
    float mysrc  = (lane < WROWS) ? __ldg(src + rowBase + r0 + lane) : 0.f;
    float myuold = EM105;

    unsigned gen = 0;

    for (int it = 0; it < MAX_ITER; ++it) {
        float accv[4][8];
        #pragma unroll
        for (int q = 0; q < 4; ++q)
            #pragma unroll
            for (int i = 0; i < 8; ++i) accv[q][i] = 0.f;
        float chm = 0.f;

        if (it == 0) {
            // ---- conversion sweep: cost -> K16, row sum (v=1), col acc ----
            for (int j = 0; j < WROWS; ++j) {
                const size_t rloc = (size_t)(r0 + j);
                const float4* Cr4 = (const float4*)cost + ((size_t)(rowBase) << 8)
                                    + (rloc << 8);
                uint2* Kw = (uint2*)(Kbase + (rloc << 10));
                float s = 0.f;
                #pragma unroll
                for (int q = 0; q < 8; ++q) {
                    float4 c = __ldcs(&Cr4[q * 32 + lane]);
                    float f0 = kexp10(c.x), f1 = kexp10(c.y);
                    float f2 = kexp10(c.z), f3 = kexp10(c.w);
                    __half2 h0 = __floats2half2_rn(f0, f1);
                    __half2 h1 = __floats2half2_rn(f2, f3);
                    uint2 pk;
                    pk.x = *(unsigned*)&h0; pk.y = *(unsigned*)&h1;
                    Kw[q * 32 + lane] = pk;
                    s += (f0 + f1) + (f2 + f3);
                }
                #pragma unroll
                for (int o = 16; o; o >>= 1) s += __shfl_xor_sync(~0u, s, o);
                float srcv = __shfl_sync(~0u, mysrc, j);
                float nu = (srcv + 1e-12f) / s;
                if (lane == j) {
                    chm = fmaxf(chm, fabsf(logf(nu / myuold)));
                    myuold = nu;
                }
                // col acc: reload just-written row from L1, iteration layout
                const uint4* Kr = (const uint4*)(Kbase + (rloc << 10));
                #pragma unroll
                for (int q = 0; q < 4; ++q) {
                    uint4 kq = Kr[q * 32 + lane];
                    float2 a = __half22float2(*(__half2*)&kq.x);
                    float2 bb = __half22float2(*(__half2*)&kq.y);
                    float2 cc = __half22float2(*(__half2*)&kq.z);
                    float2 dd = __half22float2(*(__half2*)&kq.w);
                    accv[q][0] = fmaf(a.x,  nu, accv[q][0]);
                    accv[q][1] = fmaf(a.y,  nu, accv[q][1]);
                    accv[q][2] = fmaf(bb.x, nu, accv[q][2]);
                    accv[q][3] = fmaf(bb.y, nu, accv[q][3]);
                    accv[q][4] = fmaf(cc.x, nu, accv[q][4]);
                    accv[q][5] = fmaf(cc.y, nu, accv[q][5]);
                    accv[q][6] = fmaf(dd.x, nu, accv[q][6]);
                    accv[q][7] = fmaf(dd.y, nu, accv[q][7]);
                }
            }
        } else {
            // ---- single-touch sweep: row dot + col acc per row, no syncs ----
            for (int j = 0; j < WROWS; ++j) {
                const uint4* Kr = (const uint4*)(Kbase + ((size_t)(r0 + j) << 10));
                uint4 kq0 = Kr[lane],      kq1 = Kr[32 + lane];
                uint4 kq2 = Kr[64 + lane], kq3 = Kr[96 + lane];
                float f[4][8];
                uint4 kqs[4] = {kq0, kq1, kq2, kq3};
                #pragma unroll
                for (int q = 0; q < 4; ++q) {
                    float2 a = __half22float2(*(__half2*)&kqs[q].x);
                    float2 bb = __half22float2(*(__half2*)&kqs[q].y);
                    float2 cc = __half22float2(*(__half2*)&kqs[q].z);
                    float2 dd = __half22float2(*(__half2*)&kqs[q].w);
                    f[q][0] = a.x;  f[q][1] = a.y;
                    f[q][2] = bb.x; f[q][3] = bb.y;
                    f[q][4] = cc.x; f[q][5] = cc.y;
                    f[q][6] = dd.x; f[q][7] = dd.y;
                }
                float s = 0.f;
                #pragma unroll
                for (int q = 0; q < 4; ++q) {
                    int vi = (q * 32 + lane) * 2;
                    float4 va = sv4[vi], vb = sv4[vi + 1];
                    s += f[q][0] * va.x + f[q][1] * va.y
                       + f[q][2] * va.z + f[q][3] * va.w
                       + f[q][4] * vb.x + f[q][5] * vb.y
                       + f[q][6] * vb.z + f[q][7] * vb.w;
                }
                #pragma unroll
                for (int o = 16; o; o >>= 1) s += __shfl_xor_sync(~0u, s, o);
                float srcv = __shfl_sync(~0u, mysrc, j);
                float nu = (srcv + 1e-12f) / s;
                if (lane == j) {
                    chm = fmaxf(chm, fabsf(logf(nu / myuold)));
                    myuold = nu;
                }
                #pragma unroll
                for (int q = 0; q < 4; ++q)
                    #pragma unroll
                    for (int i = 0; i < 8; ++i)
                        accv[q][i] = fmaf(f[q][i], nu, accv[q][i]);
            }
        }

        // ---- stage per-warp column partials; change reduce ----
        #pragma unroll
        for (int q = 0; q < 4; ++q) {
            *(float4*)&sacc[w][q * 256 + lane * 8] =
                make_float4(accv[q][0], accv[q][1], accv[q][2], accv[q][3]);
            *(float4*)&sacc[w][q * 256 + lane * 8 + 4] =
                make_float4(accv[q][4], accv[q][5], accv[q][6], accv[q][7]);
        }
        #pragma unroll
        for (int o = 16; o; o >>= 1)
            chm = fmaxf(chm, __shfl_xor_sync(~0u, chm, o));
        if (lane == 0) schg[w] = chm;
        __syncthreads();

        // cross-warp column reduce -> block partial (thread t: cols 4t..4t+3)
        {
            float4 pa = make_float4(0.f, 0.f, 0.f, 0.f);
            #pragma unroll
            for (int ww = 0; ww < 8; ++ww) {
                float4 x = *(const float4*)&sacc[ww][4 * t];
                pa.x += x.x; pa.y += x.y; pa.z += x.z; pa.w += x.w;
            }
            *(float4*)(g_partial[it & 1] + (size_t)blk * M + 4 * t) = pa;
        }
        if (t == 0) {
            float m = schg[0];
            #pragma unroll
            for (int i = 1; i < 8; ++i) m = fmaxf(m, schg[i]);
            atomicMax(&g_chgBatch[it * B + b], __float_as_int(m));
        }

        batchBarrier(b, gen); ++gen;

        // leader publishes batch change to global slot (overlaps v-slice)
        if (sl == 0 && t == 0) {
            int cb = __ldcg(&g_chgBatch[it * B + b]);
            atomicMax(&g_change[it], cb);
            __threadfence();
            atomicAdd(&g_chgCount[it], 1);
        }
        // v-slice: this block owns cols [sl*128, sl*128+128)
        if (t < 128) {
            int c = (sl << 7) + t;
            const float* pb = g_partial[it & 1] + (size_t)(b * BPB) * M + c;
            float ssum = 0.f;
            #pragma unroll
            for (int k = 0; k < BPB; ++k) ssum += __ldcg(pb + (size_t)k * M);
            g_vbuf[it & 1][(b << 10) + c] =
                (__ldg(tgt + (b << 10) + c) + 1e-12f) / ssum;
        }

        batchBarrier(b, gen); ++gen;

        // load full v into smem
        {
            const float* vbp = g_vbuf[it & 1] + (b << 10);
            #pragma unroll
            for (int c = t; c < M; c += TPB) sv[c] = __ldcg(vbp + c);
        }
        // global convergence decision
        if (t == 0) {
            while (*(volatile int*)&g_chgCount[it] < B) __nanosleep(128);
            sbrk = (__int_as_float(__ldcg(&g_change[it])) < TOL) ? 1 : 0;
        }
        __syncthreads();
        if (sbrk) break;
    }

    // publish final u' for epilogue
    if (lane < WROWS) suAll[r0 + lane] = myuold;
    __syncthreads();

    // ---- epilogue: T = u' * K16 * v (K16 from L2, streaming stores) ----
    {
        const uint4* Kr = (const uint4*)(g_K16 + elemBase);
        float4* Ow = (float4*)(out + elemBase);
        #pragma unroll 2
        for (int k = 0; k < 64; ++k) {
            int i = k * TPB + t;                  // uint4 idx in 128x1024 slice
            uint4 kq = Kr[i];
            float u = suAll[i >> 7];
            float4 va = sv4[(i & 127) * 2], vb = sv4[(i & 127) * 2 + 1];
            float2 f0 = __half22float2(*(__half2*)&kq.x);
            float2 f1 = __half22float2(*(__half2*)&kq.y);
            float2 f2 = __half22float2(*(__half2*)&kq.z);
            float2 f3 = __half22float2(*(__half2*)&kq.w);
            float4 o0, o1;
            o0.x = u * f0.x * va.x;
            o0.y = u * f0.y * va.y;
            o0.z = u * f1.x * va.z;
            o0.w = u * f1.y * va.w;
            o1.x = u * f2.x * vb.x;
            o1.y = u * f2.y * vb.y;
            o1.z = u * f3.x * vb.z;
            o1.w = u * f3.y * vb.w;
            __stcs(Ow + 2 * i,     o0);
            __stcs(Ow + 2 * i + 1, o1);
        }
    }
}

// ---------------------------------------------------------------------------
extern "C" void kernel_launch(void* const* d_in, const int* in_sizes, int n_in,
                              void* d_out, int out_size) {
    const float* cost = (const float*)d_in[0];
    const float* src  = (const float*)d_in[1];
    const float* tgt  = (const float*)d_in[2];
    float* out = (float*)d_out;

    initKernel<<<1, 256>>>();
    sinkhornKernel<<<GRID, TPB>>>(cost, src, tgt, out);
}

// round 12
// speedup vs baseline: 1.2943x; 1.2943x over previous
#include <cuda_runtime.h>
#include <cuda_fp16.h>
#include <cstdint>

#define B 32
#define N 1024
#define M 1024
#define TOL 0.001f
#define MAX_ITER 50
#define GRID 256               // 8 blocks/batch; 2 blocks/SM co-resident
#define TPB 512
#define RPB 128                // rows per block
#define EM105 2.7536449349747158e-5f   // exp(-10.5): scaled-u init (log_u0 = 0)

// ---------------------------------------------------------------------------
__device__ __half   g_K16[(size_t)B * N * M];    // 64 MB: e^10.5*exp(-20c), L2-resident
__device__ float    g_partial[2 * GRID * M];     // double-buffered col partials
__device__ int      g_change[MAX_ITER];          // per-iter max |dlog u| (float bits)
__device__ unsigned g_barCount;
__device__ unsigned g_barGen;

__global__ void initKernel() {
    int i = threadIdx.x;
    if (i < MAX_ITER) g_change[i] = 0;
    if (i == 0) { g_barCount = 0u; g_barGen = 0u; }
}

__device__ __forceinline__ float dot8(uint4 kq, float4 va, float4 vb) {
    float2 f0 = __half22float2(*(__half2*)&kq.x);
    float2 f1 = __half22float2(*(__half2*)&kq.y);
    float2 f2 = __half22float2(*(__half2*)&kq.z);
    float2 f3 = __half22float2(*(__half2*)&kq.w);
    return f0.x*va.x + f0.y*va.y + f1.x*va.z + f1.y*va.w
         + f2.x*vb.x + f2.y*vb.y + f3.x*vb.z + f3.y*vb.w;
}

__device__ __forceinline__ void gridBarrier(unsigned gen) {
    __syncthreads();
    if (threadIdx.x == 0) {
        __threadfence();
        if (atomicAdd(&g_barCount, 1u) == GRID - 1) {
            atomicExch(&g_barCount, 0u);
            __threadfence();
            atomicExch(&g_barGen, gen + 1u);
        } else {
            while (atomicAdd(&g_barGen, 0u) < gen + 1u) { __nanosleep(64); }
        }
        __threadfence();
    }
    __syncthreads();
}

// ---------------------------------------------------------------------------
// Persistent fused Sinkhorn.
//  prologue: convert cost->K16 (MUFU expf) per 16-row group with smem staging;
//            computes u1 per row (shuffle sum, v0=1) AND iteration-0 col acc.
//  it>=1:    R6 phased sweep: row dots (L2) + col acc (L1) per 32-row group.
//  tail:     stage col partials -> block partial -> 1 grid barrier -> v -> check.
//  epilogue: T = u' * K16 * v (streaming stores).
// ---------------------------------------------------------------------------
__global__ void __launch_bounds__(TPB, 2) sinkhornKernel(
    const float* __restrict__ cost, const float* __restrict__ src,
    const float* __restrict__ tgt, float* __restrict__ out) {

    __shared__ float sv[M];                        // v for this batch
    __shared__ __align__(16) char sbuf[16 * M * 2];// 32KB union: stage / sacc
    __shared__ float suAll[RPB];                   // scaled u' for block's rows
    __shared__ float ssrc[RPB];                    // src + 1e-12, cached
    __shared__ float schg[16];

    __half (*stage)[M] = (__half(*)[M])sbuf;       // [16][1024] halves (32KB)
    float  (*sacc)[M]  = (float (*)[M])sbuf;       // [4][1024] floats (16KB)

    const int t    = threadIdx.x;
    const int w    = t >> 5;
    const int lane = t & 31;
    const int blk  = blockIdx.x;
    const int b    = blk >> 3;
    const int sl   = blk & 7;
    const int rowBase = (b << 10) + (sl << 7);
    const size_t elemBase = (size_t)rowBase << 10;
    const int cg = t & 127, rs = t >> 7;

    const float4* sv4 = (const float4*)sv;

    if (t < RPB) ssrc[t] = __ldg(src + rowBase + t) + 1e-12f;
    __syncthreads();

    float accv[8];
    #pragma unroll
    for (int j = 0; j < 8; ++j) accv[j] = 0.f;
    float chm = 0.f;

    // ---- prologue: conversion fused with u1 + iteration-0 col acc ----
    {
        const float4* Cb = (const float4*)(cost + elemBase);
        for (int g = 0; g < 8; ++g) {              // 16-row groups
            int r = (g << 4) + w;                  // warp w owns row r (16 warps)
            const float4* Cr = Cb + ((size_t)r << 8);
            uint4* Kw = (uint4*)(g_K16 + elemBase + ((size_t)r << 10));
            uint4* Sw = (uint4*)stage[w];
            float s = 0.f;
            #pragma unroll
            for (int i = 0; i < 4; ++i) {
                int idx = i * 32 + lane;
                float4 c0 = __ldcs(&Cr[2 * idx]);
                float4 c1 = __ldcs(&Cr[2 * idx + 1]);
                float f0 = __expf(fmaf(c0.x, -20.f, 10.5f));
                float f1 = __expf(fmaf(c0.y, -20.f, 10.5f));
                float f2 = __expf(fmaf(c0.z, -20.f, 10.5f));
                float f3 = __expf(fmaf(c0.w, -20.f, 10.5f));
                float f4 = __expf(fmaf(c1.x, -20.f, 10.5f));
                float f5 = __expf(fmaf(c1.y, -20.f, 10.5f));
                float f6 = __expf(fmaf(c1.z, -20.f, 10.5f));
                float f7 = __expf(fmaf(c1.w, -20.f, 10.5f));
                s += ((f0 + f1) + (f2 + f3)) + ((f4 + f5) + (f6 + f7));
                __half2 h0 = __floats2half2_rn(f0, f1);
                __half2 h1 = __floats2half2_rn(f2, f3);
                __half2 h2 = __floats2half2_rn(f4, f5);
                __half2 h3 = __floats2half2_rn(f6, f7);
                uint4 pk;
                pk.x = *(unsigned*)&h0; pk.y = *(unsigned*)&h1;
                pk.z = *(unsigned*)&h2; pk.w = *(unsigned*)&h3;
                Kw[idx] = pk;
                Sw[idx] = pk;
            }
            #pragma unroll
            for (int o = 16; o; o >>= 1) s += __shfl_xor_sync(~0u, s, o);
            if (lane == 0) {
                float nu = ssrc[r] / s;            // v0 = 1 => rowdot = rowsum
                suAll[r] = nu;
                chm = fmaxf(chm, fabsf(logf(nu / EM105)));
            }
            __syncthreads();
            // it-0 col acc from staged halves (bit-identical to K16)
            #pragma unroll
            for (int j = 0; j < 4; ++j) {
                int rr = (rs << 2) + j;
                uint4 kq = ((const uint4*)stage[rr])[cg];
                float uu = suAll[(g << 4) + rr];
                float2 a  = __half22float2(*(__half2*)&kq.x);
                float2 bb = __half22float2(*(__half2*)&kq.y);
                float2 cc = __half22float2(*(__half2*)&kq.z);
                float2 dd = __half22float2(*(__half2*)&kq.w);
                accv[0] = fmaf(a.x,  uu, accv[0]);
                accv[1] = fmaf(a.y,  uu, accv[1]);
                accv[2] = fmaf(bb.x, uu, accv[2]);
                accv[3] = fmaf(bb.y, uu, accv[3]);
                accv[4] = fmaf(cc.x, uu, accv[4]);
                accv[5] = fmaf(cc.y, uu, accv[5]);
                accv[6] = fmaf(dd.x, uu, accv[6]);
                accv[7] = fmaf(dd.y, uu, accv[7]);
            }
            __syncthreads();
        }
    }

    unsigned gen = 0;

    for (int it = 0; it < MAX_ITER; ++it) {
        if (it > 0) {
            #pragma unroll
            for (int j = 0; j < 8; ++j) accv[j] = 0.f;
            chm = 0.f;

            #pragma unroll
            for (int g = 0; g < 4; ++g) {          // 32-row groups
                // --- row dots: warp w handles rows r0, r0+1 ---
                int r0 = (g << 5) + (w << 1);
                const uint4* K0 = (const uint4*)g_K16
                                  + ((size_t)(rowBase + r0) << 7);
                float s0 = 0.f, s1 = 0.f;
                #pragma unroll
                for (int i = 0; i < 4; ++i) {
                    int ci = i * 32 + lane;
                    uint4 ka = K0[ci], kb = K0[128 + ci];
                    float4 va = sv4[2 * ci], vb = sv4[2 * ci + 1];
                    s0 += dot8(ka, va, vb);
                    s1 += dot8(kb, va, vb);
                }
                #pragma unroll
                for (int o = 16; o; o >>= 1) {
                    s0 += __shfl_xor_sync(~0u, s0, o);
                    s1 += __shfl_xor_sync(~0u, s1, o);
                }
                if (lane == 0) {
                    float o0 = suAll[r0], o1 = suAll[r0 + 1];
                    float n0 = ssrc[r0]     / s0;
                    float n1 = ssrc[r0 + 1] / s1;
                    suAll[r0] = n0; suAll[r0 + 1] = n1;
                    chm = fmaxf(chm,
                          fmaxf(fabsf(logf(n0 / o0)), fabsf(logf(n1 / o1))));
                }
                __syncthreads();
                // --- col acc: thread (cg,rs): cols cg*8..+7 over 8 rows (L1) ---
                {
                    int rr0 = (g << 5) + (rs << 3);
                    const uint4* Kc = (const uint4*)g_K16
                        + ((size_t)(rowBase + rr0) << 7) + cg;
                    #pragma unroll
                    for (int j = 0; j < 8; ++j) {
                        uint4 kq = Kc[(size_t)j << 7];
                        float uu = suAll[rr0 + j];
                        float2 a  = __half22float2(*(__half2*)&kq.x);
                        float2 bb = __half22float2(*(__half2*)&kq.y);
                        float2 cc = __half22float2(*(__half2*)&kq.z);
                        float2 dd = __half22float2(*(__half2*)&kq.w);
                        accv[0] = fmaf(a.x,  uu, accv[0]);
                        accv[1] = fmaf(a.y,  uu, accv[1]);
                        accv[2] = fmaf(bb.x, uu, accv[2]);
                        accv[3] = fmaf(bb.y, uu, accv[3]);
                        accv[4] = fmaf(cc.x, uu, accv[4]);
                        accv[5] = fmaf(cc.y, uu, accv[5]);
                        accv[6] = fmaf(dd.x, uu, accv[6]);
                        accv[7] = fmaf(dd.y, uu, accv[7]);
                    }
                }
            }
        }

        // ---- tail: stage partials, combine, publish change ----
        #pragma unroll
        for (int j = 0; j < 8; ++j) sacc[rs][cg * 8 + j] = accv[j];
        if (lane == 0) schg[w] = chm;
        __syncthreads();
        {
            float* pp = g_partial + ((size_t)(it & 1) * GRID + blk) * M;
            #pragma unroll
            for (int c = t; c < M; c += TPB)
                pp[c] = (sacc[0][c] + sacc[1][c]) + (sacc[2][c] + sacc[3][c]);
        }
        if (t == 0) {
            float m = schg[0];
            #pragma unroll
            for (int i = 1; i < 16; ++i) m = fmaxf(m, schg[i]);
            atomicMax(&g_change[it], __float_as_int(m));
        }

        gridBarrier(gen); ++gen;

        // ---- v-phase: every block of batch b builds full v ----
        {
            const float* pb = g_partial
                + ((size_t)(it & 1) * GRID + (b << 3)) * M;
            #pragma unroll
            for (int c = t; c < M; c += TPB) {
                float ssum = 0.f;
                #pragma unroll
                for (int k = 0; k < 8; ++k) ssum += __ldcg(pb + k * M + c);
                sv[c] = (__ldg(tgt + (b << 10) + c) + 1e-12f) / ssum;
            }
        }
        float ch = __int_as_float(__ldcg(&g_change[it]));
        __syncthreads();            // sv complete before next iter / epilogue
        if (ch < TOL) break;        // uniform across grid
    }

    // ---- epilogue: T = u' * K16 * v (K16 from L2, streaming stores) ----
    {
        const uint4* Kr = (const uint4*)(g_K16 + elemBase);
        float4* Ow = (float4*)(out + elemBase);
        #pragma unroll 2
        for (int k = 0; k < 32; ++k) {
            int i = k * TPB + t;                   // uint4 idx in 128x1024 slice
            uint4 kq = Kr[i];
            float u = suAll[i >> 7];
            float4 va = sv4[(i & 127) * 2], vb = sv4[(i & 127) * 2 + 1];
            float2 f0 = __half22float2(*(__half2*)&kq.x);
            float2 f1 = __half22float2(*(__half2*)&kq.y);
            float2 f2 = __half22float2(*(__half2*)&kq.z);
            float2 f3 = __half22float2(*(__half2*)&kq.w);
            float4 o0, o1;
            o0.x = u * f0.x * va.x;
            o0.y = u * f0.y * va.y;
            o0.z = u * f1.x * va.z;
            o0.w = u * f1.y * va.w;
            o1.x = u * f2.x * vb.x;
            o1.y = u * f2.y * vb.y;
            o1.z = u * f3.x * vb.z;
            o1.w = u * f3.y * vb.w;
            __stcs(Ow + 2 * i,     o0);
            __stcs(Ow + 2 * i + 1, o1);
        }
    }
}

// ---------------------------------------------------------------------------
extern "C" void kernel_launch(void* const* d_in, const int* in_sizes, int n_in,
                              void* d_out, int out_size) {
    const float* cost = (const float*)d_in[0];
    const float* src  = (const float*)d_in[1];
    const float* tgt  = (const float*)d_in[2];
    float* out = (float*)d_out;

    initKernel<<<1, 64>>>();
    sinkhornKernel<<<GRID, TPB>>>(cost, src, tgt, out);
}